// round 6
// baseline (speedup 1.0000x reference)
#include <cuda_runtime.h>
#include <cuda_bf16.h>
#include <cstddef>
#include <cstdint>
#include <math.h>

// ---------------- problem constants ----------------
#define Lc   4
#define Hc   2048
#define NHc  16
#define NKVc 4
#define DHc  128
#define Fc   5632
#define Rc   16
#define Bc   4
#define Sc   512
#define NCc  2
#define MTc  (Bc * Sc)          // 2048 tokens
#define QNc  (NHc * DHc)        // 2048
#define KNc  (NKVc * DHc)       // 512
#define LORA_SCALE 2.0f
#define INV_SQRT_DH 0.08838834764831845f

// per-layer transposed weight buffer offsets (elements)
#define WOFF_Q 0
#define WOFF_K (WOFF_Q + Hc * QNc)
#define WOFF_V (WOFF_K + Hc * KNc)
#define WOFF_O (WOFF_V + Hc * KNc)
#define WOFF_G (WOFF_O + QNc * Hc)
#define WOFF_U (WOFF_G + Hc * Fc)
#define WOFF_D (WOFF_U + Hc * Fc)
#define LAYER_W (WOFF_D + Fc * Hc)   // 45,088,768

// ---------------- scratch (static device memory; allocation-free) ----------------
__device__ float          d_h[MTc * Hc];
__device__ float          d_x[MTc * Hc];
__device__ __nv_bfloat16  d_xh[MTc * Hc];
__device__ __nv_bfloat16  d_xl[MTc * Hc];
__device__ float          d_q[MTc * QNc];
__device__ float          d_k[MTc * KNc];
__device__ float          d_v[MTc * KNc];
__device__ float          d_t1[MTc * Rc];
__device__ float          d_t2[MTc * Rc];
__device__ float          d_t3[MTc * Rc];
__device__ float          d_sc[Bc * NHc * Sc * Sc];
__device__ float          d_ctx[MTc * QNc];
__device__ __nv_bfloat16  d_ch[MTc * QNc];
__device__ __nv_bfloat16  d_cl[MTc * QNc];
__device__ float          d_g[MTc * Fc];
__device__ float          d_u[MTc * Fc];
__device__ __nv_bfloat16  d_gh[MTc * Fc];
__device__ __nv_bfloat16  d_gl[MTc * Fc];
__device__ float          d_pooled[Bc * Hc];
__device__ float          d_cls[Bc * Hc];
__device__ __nv_bfloat16  d_whT[(size_t)Lc * LAYER_W];  // hi weights, [N,K]
__device__ __nv_bfloat16  d_wlT[(size_t)Lc * LAYER_W];  // lo weights, [N,K]

// ---------------- PTX helpers ----------------
__device__ __forceinline__ uint32_t sptr(const void* p) {
    return (uint32_t)__cvta_generic_to_shared(p);
}
#define CP_ASYNC16(dst, src) asm volatile("cp.async.cg.shared.global [%0], [%1], 16;\n" :: "r"(dst), "l"(src))
#define CP_COMMIT()          asm volatile("cp.async.commit_group;\n" ::: "memory")
#define CP_WAIT(n)           asm volatile("cp.async.wait_group %0;\n" :: "n"(n) : "memory")

__device__ __forceinline__ void mma_bf16(float* c, const uint32_t* a, const uint32_t* b) {
    asm volatile(
        "mma.sync.aligned.m16n8k16.row.col.f32.bf16.bf16.f32 "
        "{%0,%1,%2,%3}, {%4,%5,%6,%7}, {%8,%9}, {%0,%1,%2,%3};\n"
        : "+f"(c[0]), "+f"(c[1]), "+f"(c[2]), "+f"(c[3])
        : "r"(a[0]), "r"(a[1]), "r"(a[2]), "r"(a[3]), "r"(b[0]), "r"(b[1]));
}

// ---------------- weight transpose + bf16 split: W[K,N] -> hiT/loT [N,K] ----------------
__global__ void wsplit_kernel(const float* __restrict__ W,
                              __nv_bfloat16* __restrict__ hiT,
                              __nv_bfloat16* __restrict__ loT, int K, int N) {
    __shared__ float tile[32][33];
    int k0 = blockIdx.y * 32, n0 = blockIdx.x * 32;
    for (int i = threadIdx.y; i < 32; i += 8)
        tile[i][threadIdx.x] = W[(size_t)(k0 + i) * N + n0 + threadIdx.x];
    __syncthreads();
    for (int i = threadIdx.y; i < 32; i += 8) {
        float v = tile[threadIdx.x][i];
        __nv_bfloat16 hb = __float2bfloat16(v);
        float lo = v - __bfloat162float(hb);
        size_t idx = (size_t)(n0 + i) * K + k0 + threadIdx.x;
        hiT[idx] = hb;
        loT[idx] = __float2bfloat16(lo);
    }
}

// ---------------- embedding gather ----------------
__global__ void embed_kernel(const int* __restrict__ ids,
                             const float* __restrict__ emb,
                             float* __restrict__ h) {
    int row = blockIdx.x;
    const float* src = emb + (size_t)ids[row] * Hc;
    float* dst = h + (size_t)row * Hc;
    for (int i = threadIdx.x; i < Hc; i += 256) dst[i] = src[i];
}

// ---------------- rmsnorm: fp32 out + bf16 hi/lo split ----------------
__global__ void rmsnorm_kernel(const float* __restrict__ in,
                               const float* __restrict__ w,
                               float* __restrict__ out,
                               __nv_bfloat16* __restrict__ oh,
                               __nv_bfloat16* __restrict__ ol) {
    int row = blockIdx.x;
    const float* x = in + (size_t)row * Hc;
    float ss = 0.f;
    for (int i = threadIdx.x; i < Hc; i += 256) { float v = x[i]; ss += v * v; }
    __shared__ float sh[256];
    sh[threadIdx.x] = ss; __syncthreads();
    for (int o = 128; o; o >>= 1) { if (threadIdx.x < o) sh[threadIdx.x] += sh[threadIdx.x + o]; __syncthreads(); }
    float sc = rsqrtf(sh[0] / (float)Hc + 1e-6f);
    for (int i = threadIdx.x; i < Hc; i += 256) {
        float v = x[i] * sc * w[i];
        out[(size_t)row * Hc + i] = v;
        __nv_bfloat16 hb = __float2bfloat16(v);
        oh[(size_t)row * Hc + i] = hb;
        ol[(size_t)row * Hc + i] = __float2bfloat16(v - __bfloat162float(hb));
    }
}

// ---------------- bf16x3 mma.sync GEMM ----------------
// C[M,N] = (Ahi+Alo)[M,K] * (Bhi+Blo)^T  where B is [N,K] row-major (col-major k x n).
// fp32 accumulate. Optional fused: +bias, +resid, +LORA_SCALE * (loraT[M,R] @ loraB[N,R]^T).
// gridDim.z = 2 selects an independent second target (B2/bias2/loraT2/loraB2/C2), same A.
// CTA tile 128x128, k-tile 32, 256 threads = 8 warps (4M x 2N), warp tile 32x64 (2x8 mma).
// Smem tiles: [128 rows][32 k] bf16 padded to 40 elems/row (80B) -> conflict-free frag LDS.
#define APAD 40
#define TILE_B (128 * APAD * 2)      // 10240 bytes
#define STAGE_B (4 * TILE_B)         // 40960 bytes: Ah, Al, Bh, Bl
#define GEMM_SMEM (2 * STAGE_B)      // 81920 bytes

__global__ __launch_bounds__(256, 2) void gemm_bf16x3(
    const __nv_bfloat16* __restrict__ Ahi, const __nv_bfloat16* __restrict__ Alo,
    const __nv_bfloat16* __restrict__ Bhi1, const __nv_bfloat16* __restrict__ Blo1,
    const float* __restrict__ bias1, const float* __restrict__ resid1,
    const float* __restrict__ loraT1, const float* __restrict__ loraB1,
    float* __restrict__ C1,
    const __nv_bfloat16* __restrict__ Bhi2, const __nv_bfloat16* __restrict__ Blo2,
    const float* __restrict__ bias2, const float* __restrict__ resid2,
    const float* __restrict__ loraT2, const float* __restrict__ loraB2,
    float* __restrict__ C2,
    int M, int N, int K) {
    extern __shared__ uint8_t smraw[];
    const int tid = threadIdx.x;
    const int bm = blockIdx.y * 128, bn = blockIdx.x * 128;

    const __nv_bfloat16* Bhi = Bhi1; const __nv_bfloat16* Blo = Blo1;
    const float* bias = bias1; const float* resid = resid1;
    const float* loraT = loraT1; const float* loraB = loraB1;
    float* C = C1;
    if (blockIdx.z == 1) {
        Bhi = Bhi2; Blo = Blo2; bias = bias2; resid = resid2;
        loraT = loraT2; loraB = loraB2; C = C2;
    }

    const int warpId = tid >> 5, lane = tid & 31;
    const int warpM = warpId & 3, warpN = warpId >> 2;
    const int m0 = warpM * 32, n0 = warpN * 64;
    const int grp = lane >> 2, qd = lane & 3;

    // loader: thread -> row (0..127), 2 granules of 8 bf16 (16B)
    const int lrow = tid >> 1, lg0 = (tid & 1) * 2;
    const __nv_bfloat16* pAh = Ahi + (size_t)(bm + lrow) * K + lg0 * 8;
    const __nv_bfloat16* pAl = Alo + (size_t)(bm + lrow) * K + lg0 * 8;
    const __nv_bfloat16* pBh = Bhi + (size_t)(bn + lrow) * K + lg0 * 8;
    const __nv_bfloat16* pBl = Blo + (size_t)(bn + lrow) * K + lg0 * 8;
    const uint32_t sdst = sptr(smraw) + lrow * 80 + lg0 * 16;

    float acc[2][8][4];
    #pragma unroll
    for (int mt = 0; mt < 2; mt++)
        #pragma unroll
        for (int nt = 0; nt < 8; nt++)
            #pragma unroll
            for (int r = 0; r < 4; r++) acc[mt][nt][r] = 0.f;

    auto loadStage = [&](int st, int k0) {
        uint32_t d = sdst + st * STAGE_B;
        #pragma unroll
        for (int i = 0; i < 2; i++) {
            CP_ASYNC16(d + 0 * TILE_B + i * 16, pAh + k0 + i * 8);
            CP_ASYNC16(d + 1 * TILE_B + i * 16, pAl + k0 + i * 8);
            CP_ASYNC16(d + 2 * TILE_B + i * 16, pBh + k0 + i * 8);
            CP_ASYNC16(d + 3 * TILE_B + i * 16, pBl + k0 + i * 8);
        }
        CP_COMMIT();
    };

    const int KT = K >> 5;
    loadStage(0, 0);
    loadStage(1, 32);

    for (int kt = 0; kt < KT; kt++) {
        const int cur = kt & 1;
        if (kt + 1 < KT) { CP_WAIT(1); } else { CP_WAIT(0); }
        __syncthreads();

        const uint32_t* Aw = (const uint32_t*)(smraw + cur * STAGE_B);
        const uint32_t* Lw = (const uint32_t*)(smraw + cur * STAGE_B + TILE_B);
        const uint32_t* Bw = (const uint32_t*)(smraw + cur * STAGE_B + 2 * TILE_B);
        const uint32_t* Vw = (const uint32_t*)(smraw + cur * STAGE_B + 3 * TILE_B);

        #pragma unroll
        for (int ks = 0; ks < 2; ks++) {
            const int kw = ks * 8 + qd;   // word offset within row (20 words/row)
            uint32_t afH[2][4], bfH[8][2];
            #pragma unroll
            for (int mt = 0; mt < 2; mt++) {
                int r0 = (m0 + mt * 16 + grp) * 20;
                afH[mt][0] = Aw[r0 + kw];
                afH[mt][1] = Aw[r0 + 160 + kw];
                afH[mt][2] = Aw[r0 + kw + 4];
                afH[mt][3] = Aw[r0 + 160 + kw + 4];
            }
            #pragma unroll
            for (int nt = 0; nt < 8; nt++) {
                int r0 = (n0 + nt * 8 + grp) * 20;
                bfH[nt][0] = Bw[r0 + kw];
                bfH[nt][1] = Bw[r0 + kw + 4];
            }
            #pragma unroll
            for (int mt = 0; mt < 2; mt++)
                #pragma unroll
                for (int nt = 0; nt < 8; nt++)
                    mma_bf16(acc[mt][nt], afH[mt], bfH[nt]);

            uint32_t afL[2][4];
            #pragma unroll
            for (int mt = 0; mt < 2; mt++) {
                int r0 = (m0 + mt * 16 + grp) * 20;
                afL[mt][0] = Lw[r0 + kw];
                afL[mt][1] = Lw[r0 + 160 + kw];
                afL[mt][2] = Lw[r0 + kw + 4];
                afL[mt][3] = Lw[r0 + 160 + kw + 4];
            }
            #pragma unroll
            for (int mt = 0; mt < 2; mt++)
                #pragma unroll
                for (int nt = 0; nt < 8; nt++)
                    mma_bf16(acc[mt][nt], afL[mt], bfH[nt]);

            uint32_t bfL[8][2];
            #pragma unroll
            for (int nt = 0; nt < 8; nt++) {
                int r0 = (n0 + nt * 8 + grp) * 20;
                bfL[nt][0] = Vw[r0 + kw];
                bfL[nt][1] = Vw[r0 + kw + 4];
            }
            #pragma unroll
            for (int mt = 0; mt < 2; mt++)
                #pragma unroll
                for (int nt = 0; nt < 8; nt++)
                    mma_bf16(acc[mt][nt], afH[mt], bfL[nt]);
        }
        __syncthreads();

        if (kt + 2 < KT) loadStage(cur, (kt + 2) << 5);
    }

    // stage LoRA factors in smem (tiles no longer needed)
    float* sT = (float*)smraw;                 // 128 x 16 fp32 (rows of this M tile)
    float* sB = (float*)(smraw + 8192);        // 128 x 16 fp32 (cols of this N tile)
    if (loraT) {
        const float4* gT = (const float4*)(loraT + (size_t)bm * Rc);
        const float4* gB = (const float4*)(loraB + (size_t)bn * Rc);
        for (int i = tid; i < 512; i += 256) {
            ((float4*)sT)[i] = gT[i];
            ((float4*)sB)[i] = gB[i];
        }
        __syncthreads();
    }

    // epilogue
    #pragma unroll
    for (int mt = 0; mt < 2; mt++) {
        int lr0 = m0 + mt * 16 + grp;
        int lr1 = lr0 + 8;
        int row0 = bm + lr0, row1 = bm + lr1;
        #pragma unroll
        for (int nt = 0; nt < 8; nt++) {
            int lc0 = n0 + nt * 8 + 2 * qd;
            int lc1 = lc0 + 1;
            int col0 = bn + lc0, col1 = bn + lc1;
            float o00 = acc[mt][nt][0], o01 = acc[mt][nt][1];
            float o10 = acc[mt][nt][2], o11 = acc[mt][nt][3];
            if (loraT) {
                const float* t0 = sT + lr0 * Rc;
                const float* t1 = sT + lr1 * Rc;
                const float* c0 = sB + lc0 * Rc;
                const float* c1 = sB + lc1 * Rc;
                float l00 = 0.f, l01 = 0.f, l10 = 0.f, l11 = 0.f;
                #pragma unroll
                for (int r = 0; r < Rc; r++) {
                    float a0 = t0[r], a1 = t1[r], b0 = c0[r], b1 = c1[r];
                    l00 += a0 * b0; l01 += a0 * b1; l10 += a1 * b0; l11 += a1 * b1;
                }
                o00 += LORA_SCALE * l00; o01 += LORA_SCALE * l01;
                o10 += LORA_SCALE * l10; o11 += LORA_SCALE * l11;
            }
            if (bias) {
                float b0 = bias[col0], b1 = bias[col1];
                o00 += b0; o01 += b1; o10 += b0; o11 += b1;
            }
            if (resid) {
                o00 += resid[(size_t)row0 * N + col0];
                o01 += resid[(size_t)row0 * N + col1];
                o10 += resid[(size_t)row1 * N + col0];
                o11 += resid[(size_t)row1 * N + col1];
            }
            *(float2*)(C + (size_t)row0 * N + col0) = make_float2(o00, o01);
            *(float2*)(C + (size_t)row1 * N + col0) = make_float2(o10, o11);
        }
    }
}

// ---------------- LoRA down: t[m,r] = sum_k x[m,k]*A[r,k] ----------------
__global__ void lora_down_kernel(const float* __restrict__ x,
                                 const float* __restrict__ A,
                                 float* __restrict__ t, int K) {
    int m = blockIdx.x;
    int r = threadIdx.y;
    int lane = threadIdx.x;
    const float* xr = x + (size_t)m * K;
    const float* Ar = A + (size_t)r * K;
    float acc = 0.f;
    for (int k = lane; k < K; k += 32) acc += xr[k] * Ar[k];
    #pragma unroll
    for (int o = 16; o; o >>= 1) acc += __shfl_xor_sync(0xFFFFFFFFu, acc, o);
    if (lane == 0) t[m * Rc + r] = acc;
}

// ---------------- RoPE (rotate_half), in place ----------------
__global__ void rope_kernel(float* __restrict__ buf, int nheads) {
    int token = blockIdx.x;
    int head  = blockIdx.y;
    int d = threadIdx.x;
    int s = token % Sc;
    float* p = buf + ((size_t)token * nheads + head) * DHc;
    float freq = powf(1000000.0f, -(float)d / 64.0f);
    float ang = (float)s * freq;
    float sn, cs;
    sincosf(ang, &sn, &cs);
    float x1 = p[d], x2 = p[d + 64];
    p[d]      = x1 * cs - x2 * sn;
    p[d + 64] = x2 * cs + x1 * sn;
}

// ---------------- attention scores: per (b,h): S = Q K^T / sqrt(DH) ----------------
__global__ __launch_bounds__(256) void attn_scores_kernel(const float* __restrict__ qb,
                                                          const float* __restrict__ kb,
                                                          float* __restrict__ scores) {
    int bh = blockIdx.z;
    int b = bh / NHc, hd = bh % NHc;
    const float* A  = qb + ((size_t)b * Sc * NHc + hd) * DHc;
    const float* Bm = kb + ((size_t)b * Sc * NKVc + hd / (NHc / NKVc)) * DHc;
    float* C = scores + (size_t)bh * Sc * Sc;
    const int lda = NHc * DHc, ldb = NKVc * DHc;
    int bm = blockIdx.y * 64, bn = blockIdx.x * 64;
    __shared__ float As[16][64];
    __shared__ float Bs[16][64];
    int tid = threadIdx.x;
    int lr = tid >> 2, lc = (tid & 3) * 4;
    int tx = tid & 15, ty = tid >> 4;
    float acc[4][4];
    #pragma unroll
    for (int i = 0; i < 4; i++)
        #pragma unroll
        for (int j = 0; j < 4; j++) acc[i][j] = 0.f;

    for (int k0 = 0; k0 < DHc; k0 += 16) {
        float4 av = *(const float4*)(A + (size_t)(bm + lr) * lda + k0 + lc);
        As[lc + 0][lr] = av.x; As[lc + 1][lr] = av.y; As[lc + 2][lr] = av.z; As[lc + 3][lr] = av.w;
        float4 bv = *(const float4*)(Bm + (size_t)(bn + lr) * ldb + k0 + lc);
        Bs[lc + 0][lr] = bv.x; Bs[lc + 1][lr] = bv.y; Bs[lc + 2][lr] = bv.z; Bs[lc + 3][lr] = bv.w;
        __syncthreads();
        #pragma unroll
        for (int kk = 0; kk < 16; kk++) {
            float ar[4], br[4];
            #pragma unroll
            for (int i = 0; i < 4; i++) ar[i] = As[kk][ty * 4 + i];
            #pragma unroll
            for (int j = 0; j < 4; j++) br[j] = Bs[kk][tx * 4 + j];
            #pragma unroll
            for (int i = 0; i < 4; i++)
                #pragma unroll
                for (int j = 0; j < 4; j++) acc[i][j] += ar[i] * br[j];
        }
        __syncthreads();
    }
    #pragma unroll
    for (int i = 0; i < 4; i++)
        #pragma unroll
        for (int j = 0; j < 4; j++)
            C[(size_t)(bm + ty * 4 + i) * Sc + bn + tx * 4 + j] = acc[i][j] * INV_SQRT_DH;
}

// ---------------- masked softmax ----------------
__global__ void softmax_kernel(float* __restrict__ scores, const int* __restrict__ mask) {
    int row = blockIdx.x;
    int qpos = row % Sc;
    int b = row / (NHc * Sc);
    float* r = scores + (size_t)row * Sc;
    int t = threadIdx.x;
    float v[4];
    float mx = -3.0e38f;
    #pragma unroll
    for (int i = 0; i < 4; i++) {
        int k = t + 128 * i;
        bool ok = (k <= qpos) && (mask[b * Sc + k] > 0);
        v[i] = ok ? r[k] : -1e30f;
        mx = fmaxf(mx, v[i]);
    }
    __shared__ float sh[128];
    sh[t] = mx; __syncthreads();
    for (int o = 64; o; o >>= 1) { if (t < o) sh[t] = fmaxf(sh[t], sh[t + o]); __syncthreads(); }
    mx = sh[0]; __syncthreads();
    float sm = 0.f;
    #pragma unroll
    for (int i = 0; i < 4; i++) { v[i] = expf(v[i] - mx); sm += v[i]; }
    sh[t] = sm; __syncthreads();
    for (int o = 64; o; o >>= 1) { if (t < o) sh[t] += sh[t + o]; __syncthreads(); }
    float inv = 1.0f / sh[0];
    #pragma unroll
    for (int i = 0; i < 4; i++) r[t + 128 * i] = v[i] * inv;
}

// ---------------- attention context: ctx = P V  (fp32 + bf16 split out) ----------------
__global__ __launch_bounds__(256) void attn_ctx_kernel(const float* __restrict__ scores,
                                                       const float* __restrict__ vb,
                                                       float* __restrict__ ctx,
                                                       __nv_bfloat16* __restrict__ ch,
                                                       __nv_bfloat16* __restrict__ cl) {
    int bh = blockIdx.z;
    int b = bh / NHc, hd = bh % NHc;
    const float* A  = scores + (size_t)bh * Sc * Sc;
    const float* Bm = vb + ((size_t)b * Sc * NKVc + hd / (NHc / NKVc)) * DHc;
    size_t cbase = ((size_t)b * Sc * NHc + hd) * DHc;
    const int ldb = NKVc * DHc, ldc = NHc * DHc;
    int bm = blockIdx.y * 64, bn = blockIdx.x * 64;
    __shared__ float As[16][64];
    __shared__ float Bs[16][64];
    int tid = threadIdx.x;
    int tx = tid & 15, ty = tid >> 4;
    float acc[4][4];
    #pragma unroll
    for (int i = 0; i < 4; i++)
        #pragma unroll
        for (int j = 0; j < 4; j++) acc[i][j] = 0.f;

    for (int k0 = 0; k0 < Sc; k0 += 16) {
        int lr = tid >> 2, lc = (tid & 3) * 4;
        float4 av = *(const float4*)(A + (size_t)(bm + lr) * Sc + k0 + lc);
        As[lc + 0][lr] = av.x; As[lc + 1][lr] = av.y; As[lc + 2][lr] = av.z; As[lc + 3][lr] = av.w;
        int kr = tid >> 4, nc = (tid & 15) * 4;
        float4 bv = *(const float4*)(Bm + (size_t)(k0 + kr) * ldb + bn + nc);
        *(float4*)(&Bs[kr][nc]) = bv;
        __syncthreads();
        #pragma unroll
        for (int kk = 0; kk < 16; kk++) {
            float ar[4], br[4];
            #pragma unroll
            for (int i = 0; i < 4; i++) ar[i] = As[kk][ty * 4 + i];
            #pragma unroll
            for (int j = 0; j < 4; j++) br[j] = Bs[kk][tx * 4 + j];
            #pragma unroll
            for (int i = 0; i < 4; i++)
                #pragma unroll
                for (int j = 0; j < 4; j++) acc[i][j] += ar[i] * br[j];
        }
        __syncthreads();
    }
    #pragma unroll
    for (int i = 0; i < 4; i++)
        #pragma unroll
        for (int j = 0; j < 4; j++) {
            size_t idx = cbase + (size_t)(bm + ty * 4 + i) * ldc + bn + tx * 4 + j;
            float v = acc[i][j];
            ctx[idx] = v;
            __nv_bfloat16 hb = __float2bfloat16(v);
            ch[idx] = hb;
            cl[idx] = __float2bfloat16(v - __bfloat162float(hb));
        }
}

// ---------------- silu(g)*u -> bf16 hi/lo ----------------
__global__ void silu_mul_kernel(const float* __restrict__ g, const float* __restrict__ u,
                                __nv_bfloat16* __restrict__ gh, __nv_bfloat16* __restrict__ gl, int n) {
    int i = blockIdx.x * 256 + threadIdx.x;
    if (i < n) {
        float x = g[i];
        float v = (x / (1.0f + expf(-x))) * u[i];
        __nv_bfloat16 hb = __float2bfloat16(v);
        gh[i] = hb;
        gl[i] = __float2bfloat16(v - __bfloat162float(hb));
    }
}

// ---------------- final pooling + rmsnorm(lnf) ----------------
__global__ void pool_kernel(const float* __restrict__ h, const int* __restrict__ mask,
                            const float* __restrict__ lnf, float* __restrict__ pooled) {
    int b = blockIdx.x;
    int t = threadIdx.x;
    __shared__ float sh[256];
    int cnt = 0;
    for (int i = t; i < Sc; i += 256) cnt += mask[b * Sc + i];
    sh[t] = (float)cnt; __syncthreads();
    for (int o = 128; o; o >>= 1) { if (t < o) sh[t] += sh[t + o]; __syncthreads(); }
    int last = (int)sh[0] - 1;
    __syncthreads();
    const float* row = h + ((size_t)b * Sc + last) * Hc;
    float ss = 0.f;
    for (int i = t; i < Hc; i += 256) { float x = row[i]; ss += x * x; }
    sh[t] = ss; __syncthreads();
    for (int o = 128; o; o >>= 1) { if (t < o) sh[t] += sh[t + o]; __syncthreads(); }
    float sc = rsqrtf(sh[0] / (float)Hc + 1e-6f);
    for (int i = t; i < Hc; i += 256) pooled[b * Hc + i] = row[i] * sc * lnf[i];
}

// ---------------- classifier ----------------
__global__ void cls1_kernel(const float* __restrict__ pooled, const float* __restrict__ cw1,
                            const float* __restrict__ cb1, float* __restrict__ hid) {
    int n = blockIdx.x * 128 + threadIdx.x;
    int b = blockIdx.y;
    float acc = cb1[n];
    const float* p = pooled + (size_t)b * Hc;
    for (int k = 0; k < Hc; k++) acc += p[k] * cw1[(size_t)k * Hc + n];
    hid[(size_t)b * Hc + n] = fmaxf(acc, 0.f);
}

__global__ void cls2_kernel(const float* __restrict__ hid, const float* __restrict__ cw2,
                            const float* __restrict__ cb2, float* __restrict__ out) {
    int b = blockIdx.x >> 1, c = blockIdx.x & 1;
    float acc = 0.f;
    for (int k = threadIdx.x; k < Hc; k += 128) acc += hid[(size_t)b * Hc + k] * cw2[k * NCc + c];
    __shared__ float sh[128];
    sh[threadIdx.x] = acc; __syncthreads();
    for (int o = 64; o; o >>= 1) { if (threadIdx.x < o) sh[threadIdx.x] += sh[threadIdx.x + o]; __syncthreads(); }
    if (threadIdx.x == 0) out[b * NCc + c] = sh[0] + cb2[c];
}

// ---------------- host orchestration ----------------
extern "C" void kernel_launch(void* const* d_in, const int* in_sizes, int n_in,
                              void* d_out, int out_size) {
    (void)in_sizes; (void)n_in; (void)out_size;
    const int*   ids   = (const int*)d_in[0];
    const int*   mask  = (const int*)d_in[1];
    const float* embed = (const float*)d_in[2];
    const float* ln1   = (const float*)d_in[3];
    const float* wq    = (const float*)d_in[4];
    const float* bq    = (const float*)d_in[5];
    const float* wk    = (const float*)d_in[6];
    const float* bk    = (const float*)d_in[7];
    const float* wv    = (const float*)d_in[8];
    const float* bv    = (const float*)d_in[9];
    const float* wo    = (const float*)d_in[10];
    const float* laq   = (const float*)d_in[11];
    const float* lbq   = (const float*)d_in[12];
    const float* lak   = (const float*)d_in[13];
    const float* lbk   = (const float*)d_in[14];
    const float* lav   = (const float*)d_in[15];
    const float* lbv   = (const float*)d_in[16];
    const float* lao   = (const float*)d_in[17];
    const float* lbo   = (const float*)d_in[18];
    const float* ln2   = (const float*)d_in[19];
    const float* wg    = (const float*)d_in[20];
    const float* wu    = (const float*)d_in[21];
    const float* wd    = (const float*)d_in[22];
    const float* lnf   = (const float*)d_in[23];
    const float* cw1   = (const float*)d_in[24];
    const float* cb1   = (const float*)d_in[25];
    const float* cw2   = (const float*)d_in[26];
    const float* cb2   = (const float*)d_in[27];
    float* out = (float*)d_out;

    cudaFuncSetAttribute(gemm_bf16x3, cudaFuncAttributeMaxDynamicSharedMemorySize, GEMM_SMEM);

    float *h, *x, *q, *k, *v, *t1, *t2, *t3, *sc, *ctx, *g, *u, *pooled, *cls;
    __nv_bfloat16 *xh, *xl, *ch, *cl, *gh, *gl, *whT, *wlT;
    cudaGetSymbolAddress((void**)&h,   d_h);
    cudaGetSymbolAddress((void**)&x,   d_x);
    cudaGetSymbolAddress((void**)&xh,  d_xh);
    cudaGetSymbolAddress((void**)&xl,  d_xl);
    cudaGetSymbolAddress((void**)&q,   d_q);
    cudaGetSymbolAddress((void**)&k,   d_k);
    cudaGetSymbolAddress((void**)&v,   d_v);
    cudaGetSymbolAddress((void**)&t1,  d_t1);
    cudaGetSymbolAddress((void**)&t2,  d_t2);
    cudaGetSymbolAddress((void**)&t3,  d_t3);
    cudaGetSymbolAddress((void**)&sc,  d_sc);
    cudaGetSymbolAddress((void**)&ctx, d_ctx);
    cudaGetSymbolAddress((void**)&ch,  d_ch);
    cudaGetSymbolAddress((void**)&cl,  d_cl);
    cudaGetSymbolAddress((void**)&g,   d_g);
    cudaGetSymbolAddress((void**)&u,   d_u);
    cudaGetSymbolAddress((void**)&gh,  d_gh);
    cudaGetSymbolAddress((void**)&gl,  d_gl);
    cudaGetSymbolAddress((void**)&pooled, d_pooled);
    cudaGetSymbolAddress((void**)&cls,    d_cls);
    cudaGetSymbolAddress((void**)&whT,    d_whT);
    cudaGetSymbolAddress((void**)&wlT,    d_wlT);

    // ---- split + transpose all weights to bf16 hi/lo [N,K] ----
    for (int l = 0; l < Lc; l++) {
        size_t lo = (size_t)l * LAYER_W;
        struct { const float* src; size_t off; int K, N; } cv[7] = {
            { wq + (size_t)l * Hc * QNc, lo + WOFF_Q, Hc,  QNc },
            { wk + (size_t)l * Hc * KNc, lo + WOFF_K, Hc,  KNc },
            { wv + (size_t)l * Hc * KNc, lo + WOFF_V, Hc,  KNc },
            { wo + (size_t)l * QNc * Hc, lo + WOFF_O, QNc, Hc  },
            { wg + (size_t)l * Hc * Fc,  lo + WOFF_G, Hc,  Fc  },
            { wu + (size_t)l * Hc * Fc,  lo + WOFF_U, Hc,  Fc  },
            { wd + (size_t)l * Fc * Hc,  lo + WOFF_D, Fc,  Hc  },
        };
        for (int i = 0; i < 7; i++) {
            dim3 gr(cv[i].N / 32, cv[i].K / 32);
            wsplit_kernel<<<gr, dim3(32, 8)>>>(cv[i].src, whT + cv[i].off, wlT + cv[i].off,
                                               cv[i].K, cv[i].N);
        }
    }

    embed_kernel<<<MTc, 256>>>(ids, embed, h);

    for (int l = 0; l < Lc; l++) {
        size_t lw = (size_t)l * LAYER_W;
        const float* LN1 = ln1 + (size_t)l * Hc;
        const float* BQ = bq + (size_t)l * QNc;
        const float* BK = bk + (size_t)l * KNc;
        const float* BV = bv + (size_t)l * KNc;
        const float* LAQ = laq + (size_t)l * Rc * Hc;  const float* LBQ = lbq + (size_t)l * QNc * Rc;
        const float* LAK = lak + (size_t)l * Rc * Hc;  const float* LBK = lbk + (size_t)l * KNc * Rc;
        const float* LAV = lav + (size_t)l * Rc * Hc;  const float* LBV = lbv + (size_t)l * KNc * Rc;
        const float* LAO = lao + (size_t)l * Rc * QNc; const float* LBO = lbo + (size_t)l * Hc * Rc;
        const float* LN2 = ln2 + (size_t)l * Hc;

        rmsnorm_kernel<<<MTc, 256>>>(h, LN1, x, xh, xl);

        lora_down_kernel<<<MTc, dim3(32, 16)>>>(x, LAQ, t1, Hc);
        lora_down_kernel<<<MTc, dim3(32, 16)>>>(x, LAK, t2, Hc);
        lora_down_kernel<<<MTc, dim3(32, 16)>>>(x, LAV, t3, Hc);

        // Q projection
        gemm_bf16x3<<<dim3(QNc / 128, MTc / 128, 1), 256, GEMM_SMEM>>>(
            xh, xl,
            whT + lw + WOFF_Q, wlT + lw + WOFF_Q, BQ, nullptr, t1, LBQ, q,
            nullptr, nullptr, nullptr, nullptr, nullptr, nullptr, nullptr,
            MTc, QNc, Hc);
        // K + V fused (z dim)
        gemm_bf16x3<<<dim3(KNc / 128, MTc / 128, 2), 256, GEMM_SMEM>>>(
            xh, xl,
            whT + lw + WOFF_K, wlT + lw + WOFF_K, BK, nullptr, t2, LBK, k,
            whT + lw + WOFF_V, wlT + lw + WOFF_V, BV, nullptr, t3, LBV, v,
            MTc, KNc, Hc);

        // RoPE
        rope_kernel<<<dim3(MTc, NHc), 64>>>(q, NHc);
        rope_kernel<<<dim3(MTc, NKVc), 64>>>(k, NKVc);

        // attention
        attn_scores_kernel<<<dim3(Sc / 64, Sc / 64, Bc * NHc), 256>>>(q, k, sc);
        softmax_kernel<<<Bc * NHc * Sc, 128>>>(sc, mask);
        attn_ctx_kernel<<<dim3(DHc / 64, Sc / 64, Bc * NHc), 256>>>(sc, v, ctx, ch, cl);

        // O projection: h = h + ctx@WO + lora
        lora_down_kernel<<<MTc, dim3(32, 16)>>>(ctx, LAO, t1, QNc);
        gemm_bf16x3<<<dim3(Hc / 128, MTc / 128, 1), 256, GEMM_SMEM>>>(
            ch, cl,
            whT + lw + WOFF_O, wlT + lw + WOFF_O, nullptr, h, t1, LBO, h,
            nullptr, nullptr, nullptr, nullptr, nullptr, nullptr, nullptr,
            MTc, Hc, QNc);

        // MLP
        rmsnorm_kernel<<<MTc, 256>>>(h, LN2, x, xh, xl);
        gemm_bf16x3<<<dim3(Fc / 128, MTc / 128, 2), 256, GEMM_SMEM>>>(
            xh, xl,
            whT + lw + WOFF_G, wlT + lw + WOFF_G, nullptr, nullptr, nullptr, nullptr, g,
            whT + lw + WOFF_U, wlT + lw + WOFF_U, nullptr, nullptr, nullptr, nullptr, u,
            MTc, Fc, Hc);
        silu_mul_kernel<<<(MTc * Fc) / 256, 256>>>(g, u, gh, gl, MTc * Fc);
        gemm_bf16x3<<<dim3(Hc / 128, MTc / 128, 1), 256, GEMM_SMEM>>>(
            gh, gl,
            whT + lw + WOFF_D, wlT + lw + WOFF_D, nullptr, h, nullptr, nullptr, h,
            nullptr, nullptr, nullptr, nullptr, nullptr, nullptr, nullptr,
            MTc, Hc, Fc);
    }

    pool_kernel<<<Bc, 256>>>(h, mask, lnf, pooled);
    cls1_kernel<<<dim3(Hc / 128, Bc), 128>>>(pooled, cw1, cb1, cls);
    cls2_kernel<<<Bc * NCc, 128>>>(cls, cw2, cb2, out);
}

// round 7
// speedup vs baseline: 1.0466x; 1.0466x over previous
#include <cuda_runtime.h>
#include <cuda_bf16.h>
#include <cstddef>
#include <cstdint>
#include <math.h>

// ---------------- problem constants ----------------
#define Lc   4
#define Hc   2048
#define NHc  16
#define NKVc 4
#define DHc  128
#define Fc   5632
#define Rc   16
#define Bc   4
#define Sc   512
#define NCc  2
#define MTc  (Bc * Sc)          // 2048 tokens
#define QNc  (NHc * DHc)        // 2048
#define KNc  (NKVc * DHc)       // 512
#define LORA_SCALE 2.0f
#define INV_SQRT_DH 0.08838834764831845f

// per-layer transposed weight buffer offsets (elements)
#define WOFF_Q 0
#define WOFF_K (WOFF_Q + Hc * QNc)
#define WOFF_V (WOFF_K + Hc * KNc)
#define WOFF_O (WOFF_V + Hc * KNc)
#define WOFF_G (WOFF_O + QNc * Hc)
#define WOFF_U (WOFF_G + Hc * Fc)
#define WOFF_D (WOFF_U + Hc * Fc)
#define LAYER_W (WOFF_D + Fc * Hc)   // 45,088,768

// ---------------- scratch (static device memory; allocation-free) ----------------
__device__ float          d_h[MTc * Hc];
__device__ float          d_x[MTc * Hc];
__device__ __nv_bfloat16  d_xh[MTc * Hc];
__device__ __nv_bfloat16  d_xl[MTc * Hc];
__device__ float          d_q[MTc * QNc];
__device__ float          d_k[MTc * KNc];
__device__ float          d_v[MTc * KNc];
__device__ float          d_t1[MTc * Rc];
__device__ float          d_t2[MTc * Rc];
__device__ float          d_t3[MTc * Rc];
__device__ float          d_sc[Bc * NHc * Sc * Sc];
__device__ float          d_ctx[MTc * QNc];
__device__ __nv_bfloat16  d_ch[MTc * QNc];
__device__ __nv_bfloat16  d_cl[MTc * QNc];
__device__ float          d_g[MTc * Fc];
__device__ float          d_u[MTc * Fc];
__device__ __nv_bfloat16  d_gh[MTc * Fc];
__device__ __nv_bfloat16  d_gl[MTc * Fc];
__device__ float          d_pooled[Bc * Hc];
__device__ float          d_cls[Bc * Hc];
__device__ __nv_bfloat16  d_whT[(size_t)Lc * LAYER_W];  // hi weights, [N,K]
__device__ __nv_bfloat16  d_wlT[(size_t)Lc * LAYER_W];  // lo weights, [N,K]

// ---------------- PTX helpers ----------------
__device__ __forceinline__ uint32_t sptr(const void* p) {
    return (uint32_t)__cvta_generic_to_shared(p);
}
#define CP_ASYNC16(dst, src) asm volatile("cp.async.cg.shared.global [%0], [%1], 16;\n" :: "r"(dst), "l"(src))
#define CP_COMMIT()          asm volatile("cp.async.commit_group;\n" ::: "memory")
#define CP_WAIT(n)           asm volatile("cp.async.wait_group %0;\n" :: "n"(n) : "memory")

__device__ __forceinline__ void mma_bf16(float* c, const uint32_t* a, const uint32_t* b) {
    asm volatile(
        "mma.sync.aligned.m16n8k16.row.col.f32.bf16.bf16.f32 "
        "{%0,%1,%2,%3}, {%4,%5,%6,%7}, {%8,%9}, {%0,%1,%2,%3};\n"
        : "+f"(c[0]), "+f"(c[1]), "+f"(c[2]), "+f"(c[3])
        : "r"(a[0]), "r"(a[1]), "r"(a[2]), "r"(a[3]), "r"(b[0]), "r"(b[1]));
}

__device__ __forceinline__ void ldsm4(uint32_t* r, uint32_t addr) {
    asm volatile("ldmatrix.sync.aligned.m8n8.x4.shared.b16 {%0,%1,%2,%3}, [%4];"
        : "=r"(r[0]), "=r"(r[1]), "=r"(r[2]), "=r"(r[3]) : "r"(addr));
}

// ---------------- weight transpose + bf16 split: W[K,N] -> hiT/loT [N,K] ----------------
__global__ void wsplit_kernel(const float* __restrict__ W,
                              __nv_bfloat16* __restrict__ hiT,
                              __nv_bfloat16* __restrict__ loT, int K, int N) {
    __shared__ float tile[32][33];
    int k0 = blockIdx.y * 32, n0 = blockIdx.x * 32;
    for (int i = threadIdx.y; i < 32; i += 8)
        tile[i][threadIdx.x] = W[(size_t)(k0 + i) * N + n0 + threadIdx.x];
    __syncthreads();
    for (int i = threadIdx.y; i < 32; i += 8) {
        float v = tile[threadIdx.x][i];
        __nv_bfloat16 hb = __float2bfloat16(v);
        float lo = v - __bfloat162float(hb);
        size_t idx = (size_t)(n0 + i) * K + k0 + threadIdx.x;
        hiT[idx] = hb;
        loT[idx] = __float2bfloat16(lo);
    }
}

// ---------------- embedding gather ----------------
__global__ void embed_kernel(const int* __restrict__ ids,
                             const float* __restrict__ emb,
                             float* __restrict__ h) {
    int row = blockIdx.x;
    const float* src = emb + (size_t)ids[row] * Hc;
    float* dst = h + (size_t)row * Hc;
    for (int i = threadIdx.x; i < Hc; i += 256) dst[i] = src[i];
}

// ---------------- rmsnorm: fp32 out + bf16 hi/lo split ----------------
__global__ void rmsnorm_kernel(const float* __restrict__ in,
                               const float* __restrict__ w,
                               float* __restrict__ out,
                               __nv_bfloat16* __restrict__ oh,
                               __nv_bfloat16* __restrict__ ol) {
    int row = blockIdx.x;
    const float* x = in + (size_t)row * Hc;
    float ss = 0.f;
    for (int i = threadIdx.x; i < Hc; i += 256) { float v = x[i]; ss += v * v; }
    __shared__ float sh[256];
    sh[threadIdx.x] = ss; __syncthreads();
    for (int o = 128; o; o >>= 1) { if (threadIdx.x < o) sh[threadIdx.x] += sh[threadIdx.x + o]; __syncthreads(); }
    float sc = rsqrtf(sh[0] / (float)Hc + 1e-6f);
    for (int i = threadIdx.x; i < Hc; i += 256) {
        float v = x[i] * sc * w[i];
        out[(size_t)row * Hc + i] = v;
        __nv_bfloat16 hb = __float2bfloat16(v);
        oh[(size_t)row * Hc + i] = hb;
        ol[(size_t)row * Hc + i] = __float2bfloat16(v - __bfloat162float(hb));
    }
}

// ---------------- bf16x3 mma.sync GEMM, ldmatrix + 3-stage cp.async ----------------
// C[M,N] = (Ahi+Alo)[M,K] * (Bhi+Blo)^T  (B stored [N,K] row-major).
// Optional fused: +bias, +resid, +LORA_SCALE*(loraT @ loraB^T). gridDim.z selects target 2.
// CTA 128x128, k-tile 32, 8 warps (4M x 2N), warp tile 32x64 (2x8 m16n8k16).
// Smem tile: 128 rows x 64B (32 bf16), 16B chunks swizzled c^((r>>1)&3) ->
// conflict-free ldmatrix (8 lanes -> 8 distinct 16B groups).
#define TILE_B 8192                  // 128 * 64B
#define STAGE_B (4 * TILE_B)         // Ah, Al, Bh, Bl = 32KB
#define NSTAGE 3
#define GEMM_SMEM (NSTAGE * STAGE_B) // 96KB

__global__ __launch_bounds__(256, 2) void gemm_bf16x3(
    const __nv_bfloat16* __restrict__ Ahi, const __nv_bfloat16* __restrict__ Alo,
    const __nv_bfloat16* __restrict__ Bhi1, const __nv_bfloat16* __restrict__ Blo1,
    const float* __restrict__ bias1, const float* __restrict__ resid1,
    const float* __restrict__ loraT1, const float* __restrict__ loraB1,
    float* __restrict__ C1,
    const __nv_bfloat16* __restrict__ Bhi2, const __nv_bfloat16* __restrict__ Blo2,
    const float* __restrict__ bias2, const float* __restrict__ resid2,
    const float* __restrict__ loraT2, const float* __restrict__ loraB2,
    float* __restrict__ C2,
    int M, int N, int K) {
    extern __shared__ uint8_t smraw[];
    const int tid = threadIdx.x;
    const int bm = blockIdx.y * 128, bn = blockIdx.x * 128;

    const __nv_bfloat16* Bhi = Bhi1; const __nv_bfloat16* Blo = Blo1;
    const float* bias = bias1; const float* resid = resid1;
    const float* loraT = loraT1; const float* loraB = loraB1;
    float* C = C1;
    if (blockIdx.z == 1) {
        Bhi = Bhi2; Blo = Blo2; bias = bias2; resid = resid2;
        loraT = loraT2; loraB = loraB2; C = C2;
    }

    const int warpId = tid >> 5, lane = tid & 31;
    const int warpM = warpId & 3, warpN = warpId >> 2;
    const int m0 = warpM * 32, n0 = warpN * 64;
    const int grp = lane >> 2, qd = lane & 3;

    // ldmatrix addressing: lane -> row (lane&15), chunk parity (lane>>4), swizzle
    const int lrow16 = lane & 15;
    const int lch    = lane >> 4;
    const int lsw    = (lrow16 >> 1) & 3;
    const uint32_t sb = sptr(smraw);

    // loader: thread -> row (0..127), 2 granules of 16B
    const int lrow = tid >> 1, lg0 = (tid & 1) * 2;
    const int lswz = (lrow >> 1) & 3;
    const __nv_bfloat16* pAh = Ahi + (size_t)(bm + lrow) * K;
    const __nv_bfloat16* pAl = Alo + (size_t)(bm + lrow) * K;
    const __nv_bfloat16* pBh = Bhi + (size_t)(bn + lrow) * K;
    const __nv_bfloat16* pBl = Blo + (size_t)(bn + lrow) * K;
    const uint32_t srow = sb + lrow * 64;

    float acc[2][8][4];
    #pragma unroll
    for (int mt = 0; mt < 2; mt++)
        #pragma unroll
        for (int nt = 0; nt < 8; nt++)
            #pragma unroll
            for (int r = 0; r < 4; r++) acc[mt][nt][r] = 0.f;

    auto loadStage = [&](int st, int k0) {
        uint32_t d = srow + st * STAGE_B;
        #pragma unroll
        for (int i = 0; i < 2; i++) {
            int g = lg0 + i;
            uint32_t off = (uint32_t)(g ^ lswz) << 4;
            CP_ASYNC16(d + 0 * TILE_B + off, pAh + k0 + g * 8);
            CP_ASYNC16(d + 1 * TILE_B + off, pAl + k0 + g * 8);
            CP_ASYNC16(d + 2 * TILE_B + off, pBh + k0 + g * 8);
            CP_ASYNC16(d + 3 * TILE_B + off, pBl + k0 + g * 8);
        }
        CP_COMMIT();
    };

    const int KT = K >> 5;
    loadStage(0, 0);
    if (KT > 1) loadStage(1, 32);

    for (int kt = 0; kt < KT; kt++) {
        const int st = kt % NSTAGE;
        if (kt + 1 < KT) { CP_WAIT(1); } else { CP_WAIT(0); }
        __syncthreads();
        if (kt + 2 < KT) loadStage((kt + 2) % NSTAGE, (kt + 2) << 5);

        const uint32_t tAh = sb + st * STAGE_B;
        const uint32_t tAl = tAh + TILE_B;
        const uint32_t tBh = tAh + 2 * TILE_B;
        const uint32_t tBl = tAh + 3 * TILE_B;

        #pragma unroll
        for (int ks = 0; ks < 2; ks++) {
            const uint32_t choff = (uint32_t)(((ks * 2 + lch) ^ lsw)) << 4;
            uint32_t afH[2][4], afL[2][4], bfH[8][2], bfL[8][2];
            #pragma unroll
            for (int mt = 0; mt < 2; mt++) {
                uint32_t ra = (uint32_t)(m0 + mt * 16 + lrow16) * 64 + choff;
                ldsm4(afH[mt], tAh + ra);
                ldsm4(afL[mt], tAl + ra);
            }
            #pragma unroll
            for (int np = 0; np < 4; np++) {
                uint32_t rb = (uint32_t)(n0 + np * 16 + lrow16) * 64 + choff;
                uint32_t qh[4], ql[4];
                ldsm4(qh, tBh + rb);
                ldsm4(ql, tBl + rb);
                bfH[2 * np][0] = qh[0]; bfH[2 * np + 1][0] = qh[1];
                bfH[2 * np][1] = qh[2]; bfH[2 * np + 1][1] = qh[3];
                bfL[2 * np][0] = ql[0]; bfL[2 * np + 1][0] = ql[1];
                bfL[2 * np][1] = ql[2]; bfL[2 * np + 1][1] = ql[3];
            }
            #pragma unroll
            for (int mt = 0; mt < 2; mt++)
                #pragma unroll
                for (int nt = 0; nt < 8; nt++)
                    mma_bf16(acc[mt][nt], afH[mt], bfH[nt]);
            #pragma unroll
            for (int mt = 0; mt < 2; mt++)
                #pragma unroll
                for (int nt = 0; nt < 8; nt++)
                    mma_bf16(acc[mt][nt], afL[mt], bfH[nt]);
            #pragma unroll
            for (int mt = 0; mt < 2; mt++)
                #pragma unroll
                for (int nt = 0; nt < 8; nt++)
                    mma_bf16(acc[mt][nt], afH[mt], bfL[nt]);
        }
    }
    __syncthreads();

    // stage LoRA factors in smem (tiles no longer needed)
    float* sT = (float*)smraw;                 // 128 x 16 fp32
    float* sB = (float*)(smraw + 8192);        // 128 x 16 fp32
    if (loraT) {
        const float4* gT = (const float4*)(loraT + (size_t)bm * Rc);
        const float4* gB = (const float4*)(loraB + (size_t)bn * Rc);
        for (int i = tid; i < 512; i += 256) {
            ((float4*)sT)[i] = gT[i];
            ((float4*)sB)[i] = gB[i];
        }
        __syncthreads();
    }

    // epilogue
    #pragma unroll
    for (int mt = 0; mt < 2; mt++) {
        int lr0 = m0 + mt * 16 + grp;
        int lr1 = lr0 + 8;
        int row0 = bm + lr0, row1 = bm + lr1;
        #pragma unroll
        for (int nt = 0; nt < 8; nt++) {
            int lc0 = n0 + nt * 8 + 2 * qd;
            int lc1 = lc0 + 1;
            int col0 = bn + lc0, col1 = bn + lc1;
            float o00 = acc[mt][nt][0], o01 = acc[mt][nt][1];
            float o10 = acc[mt][nt][2], o11 = acc[mt][nt][3];
            if (loraT) {
                const float* t0 = sT + lr0 * Rc;
                const float* t1 = sT + lr1 * Rc;
                const float* c0 = sB + lc0 * Rc;
                const float* c1 = sB + lc1 * Rc;
                float l00 = 0.f, l01 = 0.f, l10 = 0.f, l11 = 0.f;
                #pragma unroll
                for (int r = 0; r < Rc; r++) {
                    float a0 = t0[r], a1 = t1[r], b0 = c0[r], b1 = c1[r];
                    l00 += a0 * b0; l01 += a0 * b1; l10 += a1 * b0; l11 += a1 * b1;
                }
                o00 += LORA_SCALE * l00; o01 += LORA_SCALE * l01;
                o10 += LORA_SCALE * l10; o11 += LORA_SCALE * l11;
            }
            if (bias) {
                float b0 = bias[col0], b1 = bias[col1];
                o00 += b0; o01 += b1; o10 += b0; o11 += b1;
            }
            if (resid) {
                o00 += resid[(size_t)row0 * N + col0];
                o01 += resid[(size_t)row0 * N + col1];
                o10 += resid[(size_t)row1 * N + col0];
                o11 += resid[(size_t)row1 * N + col1];
            }
            *(float2*)(C + (size_t)row0 * N + col0) = make_float2(o00, o01);
            *(float2*)(C + (size_t)row1 * N + col0) = make_float2(o10, o11);
        }
    }
}

// ---------------- LoRA down (3 targets in one launch): t[m,r] = sum_k x[m,k]*A[r,k] ----------------
__global__ void lora_down3_kernel(const float* __restrict__ x,
                                  const float* __restrict__ A1, float* __restrict__ t1,
                                  const float* __restrict__ A2, float* __restrict__ t2,
                                  const float* __restrict__ A3, float* __restrict__ t3,
                                  int K) {
    int m = blockIdx.x;
    const float* A = A1; float* t = t1;
    if (blockIdx.y == 1) { A = A2; t = t2; }
    else if (blockIdx.y == 2) { A = A3; t = t3; }
    if (A == nullptr) return;
    int r = threadIdx.y;
    int lane = threadIdx.x;
    const float* xr = x + (size_t)m * K;
    const float* Ar = A + (size_t)r * K;
    float acc = 0.f;
    for (int k = lane; k < K; k += 32) acc += xr[k] * Ar[k];
    #pragma unroll
    for (int o = 16; o; o >>= 1) acc += __shfl_xor_sync(0xFFFFFFFFu, acc, o);
    if (lane == 0) t[m * Rc + r] = acc;
}

// ---------------- RoPE (rotate_half), in place ----------------
__global__ void rope_kernel(float* __restrict__ buf, int nheads) {
    int token = blockIdx.x;
    int head  = blockIdx.y;
    int d = threadIdx.x;
    int s = token % Sc;
    float* p = buf + ((size_t)token * nheads + head) * DHc;
    float freq = powf(1000000.0f, -(float)d / 64.0f);
    float ang = (float)s * freq;
    float sn, cs;
    sincosf(ang, &sn, &cs);
    float x1 = p[d], x2 = p[d + 64];
    p[d]      = x1 * cs - x2 * sn;
    p[d + 64] = x2 * cs + x1 * sn;
}

// ---------------- attention scores: per (b,h): S = Q K^T / sqrt(DH) ----------------
__global__ __launch_bounds__(256) void attn_scores_kernel(const float* __restrict__ qb,
                                                          const float* __restrict__ kb,
                                                          float* __restrict__ scores) {
    int bh = blockIdx.z;
    int b = bh / NHc, hd = bh % NHc;
    const float* A  = qb + ((size_t)b * Sc * NHc + hd) * DHc;
    const float* Bm = kb + ((size_t)b * Sc * NKVc + hd / (NHc / NKVc)) * DHc;
    float* C = scores + (size_t)bh * Sc * Sc;
    const int lda = NHc * DHc, ldb = NKVc * DHc;
    int bm = blockIdx.y * 64, bn = blockIdx.x * 64;
    __shared__ float As[16][64];
    __shared__ float Bs[16][64];
    int tid = threadIdx.x;
    int lr = tid >> 2, lc = (tid & 3) * 4;
    int tx = tid & 15, ty = tid >> 4;
    float acc[4][4];
    #pragma unroll
    for (int i = 0; i < 4; i++)
        #pragma unroll
        for (int j = 0; j < 4; j++) acc[i][j] = 0.f;

    for (int k0 = 0; k0 < DHc; k0 += 16) {
        float4 av = *(const float4*)(A + (size_t)(bm + lr) * lda + k0 + lc);
        As[lc + 0][lr] = av.x; As[lc + 1][lr] = av.y; As[lc + 2][lr] = av.z; As[lc + 3][lr] = av.w;
        float4 bv = *(const float4*)(Bm + (size_t)(bn + lr) * ldb + k0 + lc);
        Bs[lc + 0][lr] = bv.x; Bs[lc + 1][lr] = bv.y; Bs[lc + 2][lr] = bv.z; Bs[lc + 3][lr] = bv.w;
        __syncthreads();
        #pragma unroll
        for (int kk = 0; kk < 16; kk++) {
            float ar[4], br[4];
            #pragma unroll
            for (int i = 0; i < 4; i++) ar[i] = As[kk][ty * 4 + i];
            #pragma unroll
            for (int j = 0; j < 4; j++) br[j] = Bs[kk][tx * 4 + j];
            #pragma unroll
            for (int i = 0; i < 4; i++)
                #pragma unroll
                for (int j = 0; j < 4; j++) acc[i][j] += ar[i] * br[j];
        }
        __syncthreads();
    }
    #pragma unroll
    for (int i = 0; i < 4; i++)
        #pragma unroll
        for (int j = 0; j < 4; j++)
            C[(size_t)(bm + ty * 4 + i) * Sc + bn + tx * 4 + j] = acc[i][j] * INV_SQRT_DH;
}

// ---------------- masked softmax ----------------
__global__ void softmax_kernel(float* __restrict__ scores, const int* __restrict__ mask) {
    int row = blockIdx.x;
    int qpos = row % Sc;
    int b = row / (NHc * Sc);
    float* r = scores + (size_t)row * Sc;
    int t = threadIdx.x;
    float v[4];
    float mx = -3.0e38f;
    #pragma unroll
    for (int i = 0; i < 4; i++) {
        int k = t + 128 * i;
        bool ok = (k <= qpos) && (mask[b * Sc + k] > 0);
        v[i] = ok ? r[k] : -1e30f;
        mx = fmaxf(mx, v[i]);
    }
    __shared__ float sh[128];
    sh[t] = mx; __syncthreads();
    for (int o = 64; o; o >>= 1) { if (t < o) sh[t] = fmaxf(sh[t], sh[t + o]); __syncthreads(); }
    mx = sh[0]; __syncthreads();
    float sm = 0.f;
    #pragma unroll
    for (int i = 0; i < 4; i++) { v[i] = expf(v[i] - mx); sm += v[i]; }
    sh[t] = sm; __syncthreads();
    for (int o = 64; o; o >>= 1) { if (t < o) sh[t] += sh[t + o]; __syncthreads(); }
    float inv = 1.0f / sh[0];
    #pragma unroll
    for (int i = 0; i < 4; i++) r[t + 128 * i] = v[i] * inv;
}

// ---------------- attention context: ctx = P V  (fp32 + bf16 split out) ----------------
__global__ __launch_bounds__(256) void attn_ctx_kernel(const float* __restrict__ scores,
                                                       const float* __restrict__ vb,
                                                       float* __restrict__ ctx,
                                                       __nv_bfloat16* __restrict__ ch,
                                                       __nv_bfloat16* __restrict__ cl) {
    int bh = blockIdx.z;
    int b = bh / NHc, hd = bh % NHc;
    const float* A  = scores + (size_t)bh * Sc * Sc;
    const float* Bm = vb + ((size_t)b * Sc * NKVc + hd / (NHc / NKVc)) * DHc;
    size_t cbase = ((size_t)b * Sc * NHc + hd) * DHc;
    const int ldb = NKVc * DHc, ldc = NHc * DHc;
    int bm = blockIdx.y * 64, bn = blockIdx.x * 64;
    __shared__ float As[16][64];
    __shared__ float Bs[16][64];
    int tid = threadIdx.x;
    int tx = tid & 15, ty = tid >> 4;
    float acc[4][4];
    #pragma unroll
    for (int i = 0; i < 4; i++)
        #pragma unroll
        for (int j = 0; j < 4; j++) acc[i][j] = 0.f;

    for (int k0 = 0; k0 < Sc; k0 += 16) {
        int lr = tid >> 2, lc = (tid & 3) * 4;
        float4 av = *(const float4*)(A + (size_t)(bm + lr) * Sc + k0 + lc);
        As[lc + 0][lr] = av.x; As[lc + 1][lr] = av.y; As[lc + 2][lr] = av.z; As[lc + 3][lr] = av.w;
        int kr = tid >> 4, nc = (tid & 15) * 4;
        float4 bv = *(const float4*)(Bm + (size_t)(k0 + kr) * ldb + bn + nc);
        *(float4*)(&Bs[kr][nc]) = bv;
        __syncthreads();
        #pragma unroll
        for (int kk = 0; kk < 16; kk++) {
            float ar[4], br[4];
            #pragma unroll
            for (int i = 0; i < 4; i++) ar[i] = As[kk][ty * 4 + i];
            #pragma unroll
            for (int j = 0; j < 4; j++) br[j] = Bs[kk][tx * 4 + j];
            #pragma unroll
            for (int i = 0; i < 4; i++)
                #pragma unroll
                for (int j = 0; j < 4; j++) acc[i][j] += ar[i] * br[j];
        }
        __syncthreads();
    }
    #pragma unroll
    for (int i = 0; i < 4; i++)
        #pragma unroll
        for (int j = 0; j < 4; j++) {
            size_t idx = cbase + (size_t)(bm + ty * 4 + i) * ldc + bn + tx * 4 + j;
            float v = acc[i][j];
            ctx[idx] = v;
            __nv_bfloat16 hb = __float2bfloat16(v);
            ch[idx] = hb;
            cl[idx] = __float2bfloat16(v - __bfloat162float(hb));
        }
}

// ---------------- silu(g)*u -> bf16 hi/lo ----------------
__global__ void silu_mul_kernel(const float* __restrict__ g, const float* __restrict__ u,
                                __nv_bfloat16* __restrict__ gh, __nv_bfloat16* __restrict__ gl, int n) {
    int i = blockIdx.x * 256 + threadIdx.x;
    if (i < n) {
        float x = g[i];
        float v = (x / (1.0f + expf(-x))) * u[i];
        __nv_bfloat16 hb = __float2bfloat16(v);
        gh[i] = hb;
        gl[i] = __float2bfloat16(v - __bfloat162float(hb));
    }
}

// ---------------- final pooling + rmsnorm(lnf) ----------------
__global__ void pool_kernel(const float* __restrict__ h, const int* __restrict__ mask,
                            const float* __restrict__ lnf, float* __restrict__ pooled) {
    int b = blockIdx.x;
    int t = threadIdx.x;
    __shared__ float sh[256];
    int cnt = 0;
    for (int i = t; i < Sc; i += 256) cnt += mask[b * Sc + i];
    sh[t] = (float)cnt; __syncthreads();
    for (int o = 128; o; o >>= 1) { if (t < o) sh[t] += sh[t + o]; __syncthreads(); }
    int last = (int)sh[0] - 1;
    __syncthreads();
    const float* row = h + ((size_t)b * Sc + last) * Hc;
    float ss = 0.f;
    for (int i = t; i < Hc; i += 256) { float x = row[i]; ss += x * x; }
    sh[t] = ss; __syncthreads();
    for (int o = 128; o; o >>= 1) { if (t < o) sh[t] += sh[t + o]; __syncthreads(); }
    float sc = rsqrtf(sh[0] / (float)Hc + 1e-6f);
    for (int i = t; i < Hc; i += 256) pooled[b * Hc + i] = row[i] * sc * lnf[i];
}

// ---------------- classifier ----------------
__global__ void cls1_kernel(const float* __restrict__ pooled, const float* __restrict__ cw1,
                            const float* __restrict__ cb1, float* __restrict__ hid) {
    int n = blockIdx.x * 128 + threadIdx.x;
    int b = blockIdx.y;
    float acc = cb1[n];
    const float* p = pooled + (size_t)b * Hc;
    for (int k = 0; k < Hc; k++) acc += p[k] * cw1[(size_t)k * Hc + n];
    hid[(size_t)b * Hc + n] = fmaxf(acc, 0.f);
}

__global__ void cls2_kernel(const float* __restrict__ hid, const float* __restrict__ cw2,
                            const float* __restrict__ cb2, float* __restrict__ out) {
    int b = blockIdx.x >> 1, c = blockIdx.x & 1;
    float acc = 0.f;
    for (int k = threadIdx.x; k < Hc; k += 128) acc += hid[(size_t)b * Hc + k] * cw2[k * NCc + c];
    __shared__ float sh[128];
    sh[threadIdx.x] = acc; __syncthreads();
    for (int o = 64; o; o >>= 1) { if (threadIdx.x < o) sh[threadIdx.x] += sh[threadIdx.x + o]; __syncthreads(); }
    if (threadIdx.x == 0) out[b * NCc + c] = sh[0] + cb2[c];
}

// ---------------- host orchestration ----------------
extern "C" void kernel_launch(void* const* d_in, const int* in_sizes, int n_in,
                              void* d_out, int out_size) {
    (void)in_sizes; (void)n_in; (void)out_size;
    const int*   ids   = (const int*)d_in[0];
    const int*   mask  = (const int*)d_in[1];
    const float* embed = (const float*)d_in[2];
    const float* ln1   = (const float*)d_in[3];
    const float* wq    = (const float*)d_in[4];
    const float* bq    = (const float*)d_in[5];
    const float* wk    = (const float*)d_in[6];
    const float* bk    = (const float*)d_in[7];
    const float* wv    = (const float*)d_in[8];
    const float* bv    = (const float*)d_in[9];
    const float* wo    = (const float*)d_in[10];
    const float* laq   = (const float*)d_in[11];
    const float* lbq   = (const float*)d_in[12];
    const float* lak   = (const float*)d_in[13];
    const float* lbk   = (const float*)d_in[14];
    const float* lav   = (const float*)d_in[15];
    const float* lbv   = (const float*)d_in[16];
    const float* lao   = (const float*)d_in[17];
    const float* lbo   = (const float*)d_in[18];
    const float* ln2   = (const float*)d_in[19];
    const float* wg    = (const float*)d_in[20];
    const float* wu    = (const float*)d_in[21];
    const float* wd    = (const float*)d_in[22];
    const float* lnf   = (const float*)d_in[23];
    const float* cw1   = (const float*)d_in[24];
    const float* cb1   = (const float*)d_in[25];
    const float* cw2   = (const float*)d_in[26];
    const float* cb2   = (const float*)d_in[27];
    float* out = (float*)d_out;

    cudaFuncSetAttribute(gemm_bf16x3, cudaFuncAttributeMaxDynamicSharedMemorySize, GEMM_SMEM);

    float *h, *x, *q, *k, *v, *t1, *t2, *t3, *sc, *ctx, *g, *u, *pooled, *cls;
    __nv_bfloat16 *xh, *xl, *ch, *cl, *gh, *gl, *whT, *wlT;
    cudaGetSymbolAddress((void**)&h,   d_h);
    cudaGetSymbolAddress((void**)&x,   d_x);
    cudaGetSymbolAddress((void**)&xh,  d_xh);
    cudaGetSymbolAddress((void**)&xl,  d_xl);
    cudaGetSymbolAddress((void**)&q,   d_q);
    cudaGetSymbolAddress((void**)&k,   d_k);
    cudaGetSymbolAddress((void**)&v,   d_v);
    cudaGetSymbolAddress((void**)&t1,  d_t1);
    cudaGetSymbolAddress((void**)&t2,  d_t2);
    cudaGetSymbolAddress((void**)&t3,  d_t3);
    cudaGetSymbolAddress((void**)&sc,  d_sc);
    cudaGetSymbolAddress((void**)&ctx, d_ctx);
    cudaGetSymbolAddress((void**)&ch,  d_ch);
    cudaGetSymbolAddress((void**)&cl,  d_cl);
    cudaGetSymbolAddress((void**)&g,   d_g);
    cudaGetSymbolAddress((void**)&u,   d_u);
    cudaGetSymbolAddress((void**)&gh,  d_gh);
    cudaGetSymbolAddress((void**)&gl,  d_gl);
    cudaGetSymbolAddress((void**)&pooled, d_pooled);
    cudaGetSymbolAddress((void**)&cls,    d_cls);
    cudaGetSymbolAddress((void**)&whT,    d_whT);
    cudaGetSymbolAddress((void**)&wlT,    d_wlT);

    // ---- split + transpose all weights to bf16 hi/lo [N,K] ----
    for (int l = 0; l < Lc; l++) {
        size_t lo = (size_t)l * LAYER_W;
        struct { const float* src; size_t off; int K, N; } cv[7] = {
            { wq + (size_t)l * Hc * QNc, lo + WOFF_Q, Hc,  QNc },
            { wk + (size_t)l * Hc * KNc, lo + WOFF_K, Hc,  KNc },
            { wv + (size_t)l * Hc * KNc, lo + WOFF_V, Hc,  KNc },
            { wo + (size_t)l * QNc * Hc, lo + WOFF_O, QNc, Hc  },
            { wg + (size_t)l * Hc * Fc,  lo + WOFF_G, Hc,  Fc  },
            { wu + (size_t)l * Hc * Fc,  lo + WOFF_U, Hc,  Fc  },
            { wd + (size_t)l * Fc * Hc,  lo + WOFF_D, Fc,  Hc  },
        };
        for (int i = 0; i < 7; i++) {
            dim3 gr(cv[i].N / 32, cv[i].K / 32);
            wsplit_kernel<<<gr, dim3(32, 8)>>>(cv[i].src, whT + cv[i].off, wlT + cv[i].off,
                                               cv[i].K, cv[i].N);
        }
    }

    embed_kernel<<<MTc, 256>>>(ids, embed, h);

    for (int l = 0; l < Lc; l++) {
        size_t lw = (size_t)l * LAYER_W;
        const float* LN1 = ln1 + (size_t)l * Hc;
        const float* BQ = bq + (size_t)l * QNc;
        const float* BK = bk + (size_t)l * KNc;
        const float* BV = bv + (size_t)l * KNc;
        const float* LAQ = laq + (size_t)l * Rc * Hc;  const float* LBQ = lbq + (size_t)l * QNc * Rc;
        const float* LAK = lak + (size_t)l * Rc * Hc;  const float* LBK = lbk + (size_t)l * KNc * Rc;
        const float* LAV = lav + (size_t)l * Rc * Hc;  const float* LBV = lbv + (size_t)l * KNc * Rc;
        const float* LAO = lao + (size_t)l * Rc * QNc; const float* LBO = lbo + (size_t)l * Hc * Rc;
        const float* LN2 = ln2 + (size_t)l * Hc;

        rmsnorm_kernel<<<MTc, 256>>>(h, LN1, x, xh, xl);

        lora_down3_kernel<<<dim3(MTc, 3), dim3(32, 16)>>>(x, LAQ, t1, LAK, t2, LAV, t3, Hc);

        // Q projection
        gemm_bf16x3<<<dim3(QNc / 128, MTc / 128, 1), 256, GEMM_SMEM>>>(
            xh, xl,
            whT + lw + WOFF_Q, wlT + lw + WOFF_Q, BQ, nullptr, t1, LBQ, q,
            nullptr, nullptr, nullptr, nullptr, nullptr, nullptr, nullptr,
            MTc, QNc, Hc);
        // K + V fused (z dim)
        gemm_bf16x3<<<dim3(KNc / 128, MTc / 128, 2), 256, GEMM_SMEM>>>(
            xh, xl,
            whT + lw + WOFF_K, wlT + lw + WOFF_K, BK, nullptr, t2, LBK, k,
            whT + lw + WOFF_V, wlT + lw + WOFF_V, BV, nullptr, t3, LBV, v,
            MTc, KNc, Hc);

        // RoPE
        rope_kernel<<<dim3(MTc, NHc), 64>>>(q, NHc);
        rope_kernel<<<dim3(MTc, NKVc), 64>>>(k, NKVc);

        // attention
        attn_scores_kernel<<<dim3(Sc / 64, Sc / 64, Bc * NHc), 256>>>(q, k, sc);
        softmax_kernel<<<Bc * NHc * Sc, 128>>>(sc, mask);
        attn_ctx_kernel<<<dim3(DHc / 64, Sc / 64, Bc * NHc), 256>>>(sc, v, ctx, ch, cl);

        // O projection: h = h + ctx@WO + lora
        lora_down3_kernel<<<dim3(MTc, 1), dim3(32, 16)>>>(ctx, LAO, t1,
                                                          nullptr, nullptr, nullptr, nullptr, QNc);
        gemm_bf16x3<<<dim3(Hc / 128, MTc / 128, 1), 256, GEMM_SMEM>>>(
            ch, cl,
            whT + lw + WOFF_O, wlT + lw + WOFF_O, nullptr, h, t1, LBO, h,
            nullptr, nullptr, nullptr, nullptr, nullptr, nullptr, nullptr,
            MTc, Hc, QNc);

        // MLP
        rmsnorm_kernel<<<MTc, 256>>>(h, LN2, x, xh, xl);
        gemm_bf16x3<<<dim3(Fc / 128, MTc / 128, 2), 256, GEMM_SMEM>>>(
            xh, xl,
            whT + lw + WOFF_G, wlT + lw + WOFF_G, nullptr, nullptr, nullptr, nullptr, g,
            whT + lw + WOFF_U, wlT + lw + WOFF_U, nullptr, nullptr, nullptr, nullptr, u,
            MTc, Fc, Hc);
        silu_mul_kernel<<<(MTc * Fc) / 256, 256>>>(g, u, gh, gl, MTc * Fc);
        gemm_bf16x3<<<dim3(Hc / 128, MTc / 128, 1), 256, GEMM_SMEM>>>(
            gh, gl,
            whT + lw + WOFF_D, wlT + lw + WOFF_D, nullptr, h, nullptr, nullptr, h,
            nullptr, nullptr, nullptr, nullptr, nullptr, nullptr, nullptr,
            MTc, Hc, Fc);
    }

    pool_kernel<<<Bc, 256>>>(h, mask, lnf, pooled);
    cls1_kernel<<<dim3(Hc / 128, Bc), 128>>>(pooled, cw1, cb1, cls);
    cls2_kernel<<<Bc * NCc, 128>>>(cls, cw2, cb2, out);
}